// round 11
// baseline (speedup 1.0000x reference)
#include <cuda_runtime.h>
#include <math.h>

#define BN 64
#define SN 512
#define DN 768
#define HN 384
#define GN 1536
#define TN 22

// ---------------- scratch (static device globals; zero-initialized) ---------
__device__ float g_embeds[BN * SN * DN];
__device__ float g_xg[2 * SN * BN * GN];                 // [dir][t][b][4H]
__device__ float g_lstm[BN * SN * 2 * HN];               // [b][t][2H]
__device__ float g_h[2 * 2 * BN * HN];                   // fallback kernel only
__device__ int   g_n[BN];
__device__ int   g_sent[BN];
__device__ int   g_last[BN];
__device__ unsigned g_bcnt[8];                           // fallback barrier
__device__ unsigned g_bgen[8];

// ---------------- packed fp32x2 / fast math helpers ---------------------------
__device__ __forceinline__ unsigned long long fma2(unsigned long long a,
                                                   unsigned long long b,
                                                   unsigned long long c) {
    unsigned long long d;
    asm("fma.rn.f32x2 %0, %1, %2, %3;" : "=l"(d) : "l"(a), "l"(b), "l"(c));
    return d;
}
__device__ __forceinline__ float unpack_sum(unsigned long long v) {
    float lo, hi;
    asm("mov.b64 {%0, %1}, %2;" : "=f"(lo), "=f"(hi) : "l"(v));
    return lo + hi;
}
__device__ __forceinline__ float tanh_fast(float x) {
    float y;
    asm("tanh.approx.f32 %0, %1;" : "=f"(y) : "f"(x));
    return y;
}
__device__ __forceinline__ float sig_fast(float x) {
    return 0.5f * tanh_fast(0.5f * x) + 0.5f;
}
__device__ __forceinline__ unsigned smem_u32(const void* p) {
    unsigned a;
    asm("{ .reg .u64 t; cvta.to.shared.u64 t, %1; cvt.u32.u64 %0, t; }" : "=r"(a) : "l"(p));
    return a;
}

// ---------------- scoped atomics (fallback barrier) -----------------------------
__device__ __forceinline__ unsigned atom_add_acqrel(unsigned* p, unsigned v) {
    unsigned old;
    asm volatile("atom.acq_rel.gpu.global.add.u32 %0, [%1], %2;"
                 : "=r"(old) : "l"(p), "r"(v) : "memory");
    return old;
}
__device__ __forceinline__ unsigned ld_acquire(unsigned* p) {
    unsigned v;
    asm volatile("ld.acquire.gpu.global.u32 %0, [%1];" : "=r"(v) : "l"(p) : "memory");
    return v;
}
__device__ __forceinline__ void st_release_u32(unsigned* p, unsigned v) {
    asm volatile("st.release.gpu.global.u32 [%0], %1;" :: "l"(p), "r"(v) : "memory");
}

// ---------------- index helpers -------------------------------------------------
__device__ __forceinline__ long long ld_idx(const void* p, int i, bool is64) {
    return is64 ? ((const long long*)p)[i] : (long long)((const int*)p)[i];
}
__device__ __forceinline__ bool detect_is64(const void* start_ids) {
    return ((const int*)start_ids)[1] == 0;
}

// ---------------- K0: per-batch metadata ----------------------------------------
__global__ void meta_kernel(const void* start_ids, const void* masks) {
    int b = blockIdx.x;
    int tid = threadIdx.x;
    bool is64 = detect_is64(start_ids);
    __shared__ int red[256];
    int cnt = 0, sm = 0;
    for (int t = tid; t < SN; t += 256) {
        long long sv = ld_idx(start_ids, b * SN + t, is64);
        long long mv = ld_idx(masks, b * SN + t, is64);
        cnt += (sv >= 0);
        sm += (int)mv;
    }
    red[tid] = cnt; __syncthreads();
    for (int o = 128; o > 0; o >>= 1) { if (tid < o) red[tid] += red[tid + o]; __syncthreads(); }
    int ntot = red[0]; __syncthreads();
    red[tid] = sm; __syncthreads();
    for (int o = 128; o > 0; o >>= 1) { if (tid < o) red[tid] += red[tid + o]; __syncthreads(); }
    int stot = red[0];
    if (tid == 0) {
        g_n[b] = ntot;
        g_sent[b] = stot;
        long long last = 0;
        if (ntot > 0) last = ld_idx(start_ids, b * SN + ntot - 1, is64);
        g_last[b] = (int)last;
    }
}

// ---------------- K1: align gather -----------------------------------------------
__global__ void gather_kernel(const float* __restrict__ hs, const void* __restrict__ start_ids) {
    int t = blockIdx.x, b = blockIdx.y;
    int sent = g_sent[b];
    if (t >= sent) return;
    bool is64 = detect_is64(start_ids);
    int n = g_n[b];
    long long idx;
    if (t == 0)      idx = 0;
    else if (t < n)  idx = ld_idx(start_ids, b * SN + t, is64) - 1;
    else if (t == n) idx = g_last[b];
    else             idx = 0;
    if (idx < 0) idx = 0;
    if (idx > SN - 1) idx = SN - 1;
    const float4* src = (const float4*)(hs + ((size_t)b * SN + (size_t)idx) * DN);
    float4* dst = (float4*)(g_embeds + ((size_t)b * SN + t) * DN);
    dst[threadIdx.x] = src[threadIdx.x];
}

// ---------------- K2: input projection GEMM (f32x2, cp.async, 2 blocks/SM) -------
__global__ void __launch_bounds__(256, 2) proj_kernel(
    const float* __restrict__ Wf, const float* __restrict__ Wb,
    const float* __restrict__ bihf, const float* __restrict__ bhhf,
    const float* __restrict__ bihb, const float* __restrict__ bhhb)
{
    int b = blockIdx.z & 63;
    int dir = blockIdx.z >> 6;
    int sent = g_sent[b];
    int t0 = blockIdx.y * 128;
    if (t0 >= sent) return;
    int n0 = blockIdx.x * 64;

    const float* W   = dir ? Wb   : Wf;
    const float* bih = dir ? bihb : bihf;
    const float* bhh = dir ? bhhb : bhhf;

    __shared__ float As[2][128][20];
    __shared__ float Bs[2][64][20];

    int tid = threadIdx.x;
    int tx = tid & 15, ty = tid >> 4;
    int bsw = ((tx >> 3) & 1) << 2;

    unsigned long long acc[8][4];
    #pragma unroll
    for (int i = 0; i < 8; i++)
        #pragma unroll
        for (int j = 0; j < 4; j++) acc[i][j] = 0ull;

    #define PROJ_FILL(stg, kt)                                                           \
        do {                                                                             \
            _Pragma("unroll")                                                            \
            for (int f = 0; f < 2; f++) {                                                \
                int lin = tid + f * 256;                                                 \
                int row = lin >> 2;                                                      \
                int c = (lin & 3) * 4;                                                   \
                unsigned sa = (unsigned)__cvta_generic_to_shared(&As[stg][row][c]);      \
                const float* ga = &g_embeds[((size_t)b * SN + t0 + row) * DN + (kt) + c];\
                asm volatile("cp.async.ca.shared.global [%0], [%1], 16;" :: "r"(sa), "l"(ga)); \
            }                                                                            \
            {                                                                            \
                int row = tid >> 2;                                                      \
                int c = (tid & 3) * 4;                                                   \
                int cs = c ^ (((row >> 3) & 1) << 2);                                    \
                unsigned sb = (unsigned)__cvta_generic_to_shared(&Bs[stg][row][cs]);     \
                const float* gb = &W[(size_t)(n0 + row) * DN + (kt) + c];                \
                asm volatile("cp.async.ca.shared.global [%0], [%1], 16;" :: "r"(sb), "l"(gb)); \
            }                                                                            \
            asm volatile("cp.async.commit_group;");                                      \
        } while (0)

    PROJ_FILL(0, 0);
    int st = 0;
    for (int kt = 0; kt < DN; kt += 16) {
        if (kt + 16 < DN) {
            PROJ_FILL(st ^ 1, kt + 16);
            asm volatile("cp.async.wait_group 1;");
        } else {
            asm volatile("cp.async.wait_group 0;");
        }
        __syncthreads();

        #pragma unroll
        for (int k = 0; k < 16; k += 4) {
            unsigned long long b0[4], b1[4];
            #pragma unroll
            for (int j = 0; j < 4; j++) {
                ulonglong2 v = *(const ulonglong2*)&Bs[st][tx + j * 16][k ^ bsw];
                b0[j] = v.x; b1[j] = v.y;
            }
            #pragma unroll
            for (int i = 0; i < 8; i++) {
                ulonglong2 av = *(const ulonglong2*)&As[st][ty + i * 16][k];
                #pragma unroll
                for (int j = 0; j < 4; j++) {
                    acc[i][j] = fma2(av.x, b0[j], acc[i][j]);
                    acc[i][j] = fma2(av.y, b1[j], acc[i][j]);
                }
            }
        }
        __syncthreads();
        st ^= 1;
    }
    #undef PROJ_FILL

    float bsj[4];
    #pragma unroll
    for (int j = 0; j < 4; j++) {
        int n = n0 + tx + j * 16;
        bsj[j] = bih[n] + bhh[n];
    }
    #pragma unroll
    for (int i = 0; i < 8; i++) {
        int t = t0 + ty + i * 16;
        if (t < sent) {
            float* dst = &g_xg[((size_t)(dir * SN + t) * BN + b) * GN + n0 + tx];
            #pragma unroll
            for (int j = 0; j < 4; j++)
                dst[j * 16] = unpack_sum(acc[i][j]) + bsj[j];
        }
    }
}

// ---------------- K3a: LSTM via CGA cluster-16 + DSMEM h-exchange ------------------
// grid 128, cluster (16,1,1): cid = blk>>4 -> dir = cid>>2, bg = cid&3 (16 batches).
// Rank blk&15 owns 24 hidden units (96 gate rows). Whh slice stride 388 (16B-aligned
// rows). Thread rows at spacing 8 (r = rg*48 + i*8 + rs): w-LDS offsets rs*4 mod 32
// -> conflict-free; h-LDS per-phase broadcast. DSMEM scatter + HW cluster barrier.
__global__ void __launch_bounds__(256, 1) lstm_cluster_kernel(
    const float* __restrict__ Whhf, const float* __restrict__ Whhb,
    const float* __restrict__ bihf, const float* __restrict__ bhhf,
    const float* __restrict__ bihb, const float* __restrict__ bhhb,
    const float* __restrict__ h0, const float* __restrict__ c0)
{
    extern __shared__ float sm_[];
    float* ws     = sm_;                        // 96*388 = 37248
    float* hsm    = sm_ + 37248;                // 2*16*388 = 12416
    float* P      = sm_ + 37248 + 12416;        // 4*96*17 = 6528
    float* bias_s = P + 6528;                   // 96
    int*   sent_s = (int*)(bias_s + 96);        // 16

    int tid = threadIdx.x;
    int blk = blockIdx.x;
    int cid = blk >> 4;
    int dir = cid >> 2;
    int bg  = cid & 3;            // 4 batch groups of 16
    int u0  = (blk & 15) * 24;    // this rank's hidden slice

    const float* Whh = dir ? Whhb : Whhf;
    const float* bih = dir ? bihb : bihf;
    const float* bhh = dir ? bhhb : bhhf;

    // load Whh slice (stride 388: every row base 16B-aligned)
    for (int idx = tid; idx < 96 * HN; idx += 256) {
        int r = idx / HN, k = idx % HN;
        int grow = (r / 24) * HN + u0 + (r % 24);
        ws[r * 388 + k] = Whh[(size_t)grow * HN + k];
    }
    if (tid < 96) {
        int grow = (tid / 24) * HN + u0 + (tid % 24);
        bias_s[tid] = bih[grow] + bhh[grow];
    }
    if (tid < 16) sent_s[tid] = g_sent[bg * 16 + tid];

    // init hsm[0] = h0 for all 16 batches (full 384 columns, local copy)
    {
        const float* h0d = h0 + ((size_t)dir * BN + bg * 16) * HN;
        for (int idx = tid; idx < 16 * 96; idx += 256) {
            int b2 = idx / 96, k4 = (idx % 96) * 4;
            *(float4*)&hsm[b2 * 388 + k4] = *(const float4*)&h0d[(size_t)b2 * HN + k4];
        }
    }

    // cell ownership: tid < 96: cb = tid/6 (batch 0..15), cq = tid%6 (unit quad)
    bool cellv = (tid < 96);
    int cb = tid / 6, cq = tid % 6;
    int gb = bg * 16 + cb;
    float cr[4] = {0.f, 0.f, 0.f, 0.f};
    if (cellv) {
        float4 cv = *(const float4*)&c0[((size_t)dir * BN + gb) * HN + u0 + cq * 4];
        cr[0] = cv.x; cr[1] = cv.y; cr[2] = cv.z; cr[3] = cv.w;
    }

    // GEMV coords: 8 warps: ks = w>>1 (k-split 4 x 96), rg = w&1;
    // lane: bq = l>>3 (batches j*4+bq), rs = l&7; rows r = rg*48 + i*8 + rs, i=0..5
    int w    = tid >> 5;
    int ks   = w >> 1;
    int rg   = w & 1;
    int lane = tid & 31;
    int bq   = lane >> 3;
    int rs   = lane & 7;
    int kbase = ks * 96;
    int rbase = rg * 48 + rs;

    unsigned hsm_b = smem_u32(hsm);

    __syncthreads();
    asm volatile("barrier.cluster.arrive.aligned;" ::: "memory");
    asm volatile("barrier.cluster.wait.aligned;" ::: "memory");

    for (int s = 0; s < SN; s++) {
        int p = s & 1;
        int t = dir ? (SN - 1 - s) : s;

        // prefetch xg (consumed in cell)
        float4 xp[4];
        if (cellv) {
            const float* xb = &g_xg[((size_t)(dir * SN + t) * BN + gb) * GN + u0 + cq * 4];
            #pragma unroll
            for (int g = 0; g < 4; g++) xp[g] = *(const float4*)&xb[g * HN];
        }

        // GEMV: 6 rows (spacing 8) x 4 batches x 96 k from own smem, packed f32x2
        {
            const float* hb = &hsm[p * 6208 + kbase];
            const float* wb = &ws[rbase * 388 + kbase];
            unsigned long long acc[6][4];
            #pragma unroll
            for (int i = 0; i < 6; i++) {
                acc[i][0] = 0ull; acc[i][1] = 0ull; acc[i][2] = 0ull; acc[i][3] = 0ull;
            }
            #pragma unroll 4
            for (int kk = 0; kk < 96; kk += 4) {
                ulonglong2 hv0 = *(const ulonglong2*)&hb[(0 * 4 + bq) * 388 + kk];
                ulonglong2 hv1 = *(const ulonglong2*)&hb[(1 * 4 + bq) * 388 + kk];
                ulonglong2 hv2 = *(const ulonglong2*)&hb[(2 * 4 + bq) * 388 + kk];
                ulonglong2 hv3 = *(const ulonglong2*)&hb[(3 * 4 + bq) * 388 + kk];
                #pragma unroll
                for (int i = 0; i < 6; i++) {
                    ulonglong2 wv = *(const ulonglong2*)&wb[i * (8 * 388) + kk];
                    acc[i][0] = fma2(hv0.x, wv.x, acc[i][0]); acc[i][0] = fma2(hv0.y, wv.y, acc[i][0]);
                    acc[i][1] = fma2(hv1.x, wv.x, acc[i][1]); acc[i][1] = fma2(hv1.y, wv.y, acc[i][1]);
                    acc[i][2] = fma2(hv2.x, wv.x, acc[i][2]); acc[i][2] = fma2(hv2.y, wv.y, acc[i][2]);
                    acc[i][3] = fma2(hv3.x, wv.x, acc[i][3]); acc[i][3] = fma2(hv3.y, wv.y, acc[i][3]);
                }
            }
            #pragma unroll
            for (int i = 0; i < 6; i++) {
                int r = rbase + i * 8;
                #pragma unroll
                for (int j = 0; j < 4; j++)
                    P[(ks * 96 + r) * 17 + j * 4 + bq] = unpack_sum(acc[i][j]);
            }
        }
        __syncthreads();

        // cell update: 4 units per thread, then DSMEM scatter to all 16 ranks
        float4 hv4;
        if (cellv) {
            bool valid = (t < sent_s[cb]);
            float hvs[4];
            #pragma unroll
            for (int j = 0; j < 4; j++) {
                int u = cq * 4 + j;
                float g4[4];
                #pragma unroll
                for (int g = 0; g < 4; g++) {
                    int r = g * 24 + u;
                    float sum = P[(0 * 96 + r) * 17 + cb] + P[(1 * 96 + r) * 17 + cb]
                              + P[(2 * 96 + r) * 17 + cb] + P[(3 * 96 + r) * 17 + cb];
                    float x = valid ? ((const float*)&xp[g])[j] : bias_s[r];
                    g4[g] = sum + x;
                }
                float ig = sig_fast(g4[0]), fg = sig_fast(g4[1]);
                float cg = tanh_fast(g4[2]), og = sig_fast(g4[3]);
                cr[j] = fg * cr[j] + ig * cg;
                hvs[j] = og * tanh_fast(cr[j]);
            }
            hv4 = make_float4(hvs[0], hvs[1], hvs[2], hvs[3]);

            unsigned loc = hsm_b + (((p ^ 1) * 6208 + cb * 388 + u0 + cq * 4) << 2);
            #pragma unroll
            for (int rk = 0; rk < 16; rk++) {
                unsigned rem;
                asm("mapa.shared::cluster.u32 %0, %1, %2;" : "=r"(rem) : "r"(loc), "r"(rk));
                asm volatile("st.shared::cluster.v4.f32 [%0], {%1, %2, %3, %4};"
                             :: "r"(rem), "f"(hv4.x), "f"(hv4.y), "f"(hv4.z), "f"(hv4.w)
                             : "memory");
            }
        }

        asm volatile("barrier.cluster.arrive.aligned;" ::: "memory");

        // g_lstm store hidden under the cluster wait
        if (cellv)
            *(float4*)&g_lstm[((size_t)gb * SN + t) * (2 * HN) + dir * HN + u0 + cq * 4] = hv4;

        asm volatile("barrier.cluster.wait.aligned;" ::: "memory");
    }
}

// ---------------- K3b: FALLBACK — proven R7 flat-barrier LSTM ----------------------
__global__ void __launch_bounds__(256, 2) lstm_flat_kernel(
    const float* __restrict__ Whhf, const float* __restrict__ Whhb,
    const float* __restrict__ bihf, const float* __restrict__ bhhf,
    const float* __restrict__ bihb, const float* __restrict__ bhhb,
    const float* __restrict__ h0, const float* __restrict__ c0)
{
    extern __shared__ float sm_[];
    float* ws     = sm_;                          // 48*388
    float* hsm    = sm_ + 18624;                  // 16*388
    float* P      = sm_ + 18624 + 6208;           // 4*48*17
    float* bias_s = P + 3264;
    int*   sent_s = (int*)(bias_s + 48);

    int tid = threadIdx.x;
    int blk = blockIdx.x;
    int dir = blk >> 7;
    int r7  = blk & 127;
    int bg  = r7 >> 5;
    int u0  = (r7 & 31) * 12;

    const float* Whh = dir ? Whhb : Whhf;
    const float* bih = dir ? bihb : bihf;
    const float* bhh = dir ? bhhb : bhhf;

    for (int idx = tid; idx < 48 * HN; idx += 256) {
        int r = idx / HN, k = idx % HN;
        int grow = (r / 12) * HN + u0 + (r % 12);
        ws[r * 388 + k] = Whh[(size_t)grow * HN + k];
    }
    if (tid < 48) {
        int grow = (tid / 12) * HN + u0 + (tid % 12);
        bias_s[tid] = bih[grow] + bhh[grow];
    }
    if (tid < 16) sent_s[tid] = g_sent[bg * 16 + tid];

    bool cellv = (tid < 192);
    int lb = tid / 12, u = tid % 12;
    int gb = bg * 16 + lb;
    int gj = u0 + u;
    float creg = 0.f;
    if (cellv) {
        g_h[((dir * 2 + 0) * BN + gb) * HN + gj] = h0[((size_t)dir * BN + gb) * HN + gj];
        creg = c0[((size_t)dir * BN + gb) * HN + gj];
    }

    int w    = tid >> 5;
    int ks   = w >> 1;
    int rg   = w & 1;
    int lane = tid & 31;
    int bq   = lane >> 3;
    int rs   = lane & 7;
    int kbase = ks * 96;
    int r0 = rg * 24 + rs * 3;
    const float* wr0 = &ws[(r0 + 0) * 388 + kbase];
    const float* wr1 = &ws[(r0 + 1) * 388 + kbase];
    const float* wr2 = &ws[(r0 + 2) * 388 + kbase];

    int gid = dir * 4 + bg;
    unsigned my_gen = 0;
    if (tid == 0) my_gen = ld_acquire(&g_bgen[gid]);
    __syncthreads();
    if (tid == 0) {
        __threadfence();
        unsigned old = atom_add_acqrel(&g_bcnt[gid], 1u);
        if (((old + 1) & 31u) == 0u) st_release_u32(&g_bgen[gid], my_gen + 1);
        else while (ld_acquire(&g_bgen[gid]) == my_gen) { }
        my_gen++;
    }
    __syncthreads();

    for (int s = 0; s < SN; s++) {
        int p = s & 1;
        int t = dir ? (SN - 1 - s) : s;

        float xp[4];
        if (cellv) {
            const float* xb = &g_xg[((size_t)(dir * SN + t) * BN + gb) * GN + gj];
            #pragma unroll
            for (int g = 0; g < 4; g++) xp[g] = xb[g * HN];
        }
        {
            const float* hsrc = g_h + (size_t)((dir * 2 + p) * BN + bg * 16) * HN;
            #pragma unroll
            for (int c = 0; c < 6; c++) {
                int idx = lane + c * 32;
                int sb = rg * 8 + idx / 24;
                int kk = (idx % 24) * 4;
                unsigned sd = (unsigned)__cvta_generic_to_shared(&hsm[sb * 388 + kbase + kk]);
                const float* gsrc = hsrc + (size_t)sb * HN + kbase + kk;
                asm volatile("cp.async.cg.shared.global [%0], [%1], 16;" :: "r"(sd), "l"(gsrc));
            }
            asm volatile("cp.async.commit_group;");
            asm volatile("cp.async.wait_group 0;");
        }
        asm volatile("bar.sync %0, 64;" :: "r"(1 + ks) : "memory");
        {
            unsigned long long acc[3][4];
            #pragma unroll
            for (int i = 0; i < 3; i++) { acc[i][0]=0ull; acc[i][1]=0ull; acc[i][2]=0ull; acc[i][3]=0ull; }
            #pragma unroll 4
            for (int kk = 0; kk < 96; kk += 4) {
                ulonglong2 hv0 = *(const ulonglong2*)&hsm[(0 * 4 + bq) * 388 + kbase + kk];
                ulonglong2 hv1 = *(const ulonglong2*)&hsm[(1 * 4 + bq) * 388 + kbase + kk];
                ulonglong2 hv2 = *(const ulonglong2*)&hsm[(2 * 4 + bq) * 388 + kbase + kk];
                ulonglong2 hv3 = *(const ulonglong2*)&hsm[(3 * 4 + bq) * 388 + kbase + kk];
                ulonglong2 w0 = *(const ulonglong2*)(wr0 + kk);
                ulonglong2 w1 = *(const ulonglong2*)(wr1 + kk);
                ulonglong2 w2 = *(const ulonglong2*)(wr2 + kk);
                acc[0][0]=fma2(hv0.x,w0.x,acc[0][0]); acc[0][0]=fma2(hv0.y,w0.y,acc[0][0]);
                acc[0][1]=fma2(hv1.x,w0.x,acc[0][1]); acc[0][1]=fma2(hv1.y,w0.y,acc[0][1]);
                acc[0][2]=fma2(hv2.x,w0.x,acc[0][2]); acc[0][2]=fma2(hv2.y,w0.y,acc[0][2]);
                acc[0][3]=fma2(hv3.x,w0.x,acc[0][3]); acc[0][3]=fma2(hv3.y,w0.y,acc[0][3]);
                acc[1][0]=fma2(hv0.x,w1.x,acc[1][0]); acc[1][0]=fma2(hv0.y,w1.y,acc[1][0]);
                acc[1][1]=fma2(hv1.x,w1.x,acc[1][1]); acc[1][1]=fma2(hv1.y,w1.y,acc[1][1]);
                acc[1][2]=fma2(hv2.x,w1.x,acc[1][2]); acc[1][2]=fma2(hv2.y,w1.y,acc[1][2]);
                acc[1][3]=fma2(hv3.x,w1.x,acc[1][3]); acc[1][3]=fma2(hv3.y,w1.y,acc[1][3]);
                acc[2][0]=fma2(hv0.x,w2.x,acc[2][0]); acc[2][0]=fma2(hv0.y,w2.y,acc[2][0]);
                acc[2][1]=fma2(hv1.x,w2.x,acc[2][1]); acc[2][1]=fma2(hv1.y,w2.y,acc[2][1]);
                acc[2][2]=fma2(hv2.x,w2.x,acc[2][2]); acc[2][2]=fma2(hv2.y,w2.y,acc[2][2]);
                acc[2][3]=fma2(hv3.x,w2.x,acc[2][3]); acc[2][3]=fma2(hv3.y,w2.y,acc[2][3]);
            }
            #pragma unroll
            for (int i = 0; i < 3; i++)
                #pragma unroll
                for (int j = 0; j < 4; j++)
                    P[(ks * 48 + r0 + i) * 17 + j * 4 + bq] = unpack_sum(acc[i][j]);
        }
        __syncthreads();

        float hv = 0.f;
        if (cellv) {
            bool valid = (t < sent_s[lb]);
            float g4[4];
            #pragma unroll
            for (int g = 0; g < 4; g++) {
                int r = g * 12 + u;
                float sum = P[(0 * 48 + r) * 17 + lb] + P[(1 * 48 + r) * 17 + lb]
                          + P[(2 * 48 + r) * 17 + lb] + P[(3 * 48 + r) * 17 + lb];
                g4[g] = sum + (valid ? xp[g] : bias_s[r]);
            }
            float ig = sig_fast(g4[0]), fg = sig_fast(g4[1]);
            float cg = tanh_fast(g4[2]), og = sig_fast(g4[3]);
            creg = fg * creg + ig * cg;
            hv = og * tanh_fast(creg);
            g_h[((dir * 2 + (p ^ 1)) * BN + gb) * HN + gj] = hv;
        }
        __syncthreads();

        if (tid == 0) {
            __threadfence();
            unsigned old = atom_add_acqrel(&g_bcnt[gid], 1u);
            if (((old + 1) & 31u) == 0u) st_release_u32(&g_bgen[gid], my_gen + 1);
        }
        if (cellv)
            g_lstm[((size_t)gb * SN + t) * (2 * HN) + dir * HN + gj] = hv;
        if (tid == 0) {
            while (ld_acquire(&g_bgen[gid]) == my_gen) { }
            my_gen++;
        }
        __syncthreads();
    }
}

// ---------------- K4: output linear (Wlin cached in smem, 16 rows/block) ----------
__global__ void __launch_bounds__(256) out_kernel(
    const float* __restrict__ Wlin, const float* __restrict__ blin,
    float* __restrict__ out)
{
    extern __shared__ float Wl[];
    int tid = threadIdx.x;
    int lane = tid & 31, w = tid >> 5;
    for (int idx = tid; idx < TN * 768; idx += 256) Wl[idx] = Wlin[idx];
    __syncthreads();

    int base = blockIdx.x * 16;
    #pragma unroll
    for (int rr = 0; rr < 2; rr++) {
        int row = base + w * 2 + rr;
        const float* src = g_lstm + (size_t)row * 768;
        float rs[24];
        #pragma unroll
        for (int i = 0; i < 24; i++) rs[i] = src[lane + 32 * i];
        for (int o = 0; o < TN; o++) {
            const float* wr = &Wl[o * 768];
            float s = 0.f;
            #pragma unroll
            for (int i = 0; i < 24; i++) s += rs[i] * wr[lane + 32 * i];
            #pragma unroll
            for (int off = 16; off; off >>= 1) s += __shfl_down_sync(0xffffffffu, s, off);
            if (lane == 0) out[(size_t)row * TN + o] = s + blin[o];
        }
    }
}

// ---------------- launch -----------------------------------------------------------
extern "C" void kernel_launch(void* const* d_in, const int* in_sizes, int n_in,
                              void* d_out, int out_size) {
    const float* hs   = (const float*)d_in[0];
    const float* h0   = (const float*)d_in[1];
    const float* c0   = (const float*)d_in[2];
    const float* Wihf = (const float*)d_in[3];
    const float* Whhf = (const float*)d_in[4];
    const float* bihf = (const float*)d_in[5];
    const float* bhhf = (const float*)d_in[6];
    const float* Wihb = (const float*)d_in[7];
    const float* Whhb = (const float*)d_in[8];
    const float* bihb = (const float*)d_in[9];
    const float* bhhb = (const float*)d_in[10];
    const float* Wlin = (const float*)d_in[11];
    const float* blin = (const float*)d_in[12];
    const void*  sid  = d_in[13];
    const void*  msk  = d_in[14];

    meta_kernel<<<BN, 256>>>(sid, msk);
    gather_kernel<<<dim3(SN, BN), 192>>>(hs, sid);
    proj_kernel<<<dim3(GN / 64, SN / 128, 2 * BN), 256>>>(Wihf, Wihb, bihf, bhhf, bihb, bhhb);

    // --- cluster-16 DSMEM lstm; fallback to flat R7 kernel on launch failure ---
    const int clu_smem = (96 * 388 + 2 * 16 * 388 + 4 * 96 * 17 + 96 + 16) * 4;  // 225,216 B
    cudaFuncSetAttribute(lstm_cluster_kernel, cudaFuncAttributeMaxDynamicSharedMemorySize, clu_smem);
    cudaFuncSetAttribute(lstm_cluster_kernel, cudaFuncAttributeNonPortableClusterSizeAllowed, 1);

    cudaLaunchConfig_t cfg = {};
    cfg.gridDim = dim3(128, 1, 1);
    cfg.blockDim = dim3(256, 1, 1);
    cfg.dynamicSmemBytes = clu_smem;
    cfg.stream = 0;
    cudaLaunchAttribute attrs[1];
    attrs[0].id = cudaLaunchAttributeClusterDimension;
    attrs[0].val.clusterDim.x = 16;
    attrs[0].val.clusterDim.y = 1;
    attrs[0].val.clusterDim.z = 1;
    cfg.attrs = attrs;
    cfg.numAttrs = 1;

    cudaError_t e = cudaLaunchKernelEx(&cfg, lstm_cluster_kernel,
                                       Whhf, Whhb, bihf, bhhf, bihb, bhhb, h0, c0);
    if (e != cudaSuccess) {
        cudaGetLastError();  // clear
        const int flat_smem = (48 * 388 + 16 * 388 + 4 * 48 * 17 + 48 + 16) * 4;
        cudaFuncSetAttribute(lstm_flat_kernel, cudaFuncAttributeMaxDynamicSharedMemorySize, flat_smem);
        lstm_flat_kernel<<<256, 256, flat_smem>>>(Whhf, Whhb, bihf, bhhf, bihb, bhhb, h0, c0);
    }

    const int out_smem = TN * 768 * 4;
    cudaFuncSetAttribute(out_kernel, cudaFuncAttributeMaxDynamicSharedMemorySize, out_smem);
    out_kernel<<<(BN * SN) / 16, 256, out_smem>>>(Wlin, blin, (float*)d_out);
}

// round 12
// speedup vs baseline: 1.7014x; 1.7014x over previous
#include <cuda_runtime.h>
#include <cuda_bf16.h>
#include <math.h>

#define BN 64
#define SN 512
#define DN 768
#define HN 384
#define GN 1536
#define TN 22

// ---------------- scratch (static device globals; zero-initialized) ---------
__device__ __align__(256) __nv_bfloat16 g_eh[BN * SN * DN];   // embeds hi (bf16)
__device__ __align__(256) __nv_bfloat16 g_el[BN * SN * DN];   // embeds lo
__device__ __align__(256) __nv_bfloat16 g_Wh[2 * GN * DN];    // Wih hi, both dirs
__device__ __align__(256) __nv_bfloat16 g_Wl[2 * GN * DN];    // Wih lo
__device__ float g_xg[2 * SN * BN * GN];                      // [dir][t][b][4H]
__device__ float g_lstm[BN * SN * 2 * HN];                    // [b][t][2H]
__device__ float g_h[2 * 2 * BN * HN];                        // [dir][parity][b][H]
__device__ int   g_n[BN];
__device__ int   g_sent[BN];
__device__ int   g_last[BN];
__device__ unsigned g_bcnt[8];                                // monotonic, per (dir,bg)
__device__ unsigned g_bgen[8];

// ---------------- packed fp32x2 / fast math helpers ---------------------------
__device__ __forceinline__ unsigned long long fma2(unsigned long long a,
                                                   unsigned long long b,
                                                   unsigned long long c) {
    unsigned long long d;
    asm("fma.rn.f32x2 %0, %1, %2, %3;" : "=l"(d) : "l"(a), "l"(b), "l"(c));
    return d;
}
__device__ __forceinline__ float unpack_sum(unsigned long long v) {
    float lo, hi;
    asm("mov.b64 {%0, %1}, %2;" : "=f"(lo), "=f"(hi) : "l"(v));
    return lo + hi;
}
__device__ __forceinline__ float tanh_fast(float x) {
    float y;
    asm("tanh.approx.f32 %0, %1;" : "=f"(y) : "f"(x));
    return y;
}
__device__ __forceinline__ float sig_fast(float x) {
    return 0.5f * tanh_fast(0.5f * x) + 0.5f;
}

// bf16 mma: D += A(16x16,row) * B(16x8,col), fp32 accum
__device__ __forceinline__ void mma_bf16(float (&d)[4], const unsigned (&a)[4],
                                         unsigned b0, unsigned b1) {
    asm volatile(
        "mma.sync.aligned.m16n8k16.row.col.f32.bf16.bf16.f32 "
        "{%0,%1,%2,%3},{%4,%5,%6,%7},{%8,%9},{%0,%1,%2,%3};"
        : "+f"(d[0]), "+f"(d[1]), "+f"(d[2]), "+f"(d[3])
        : "r"(a[0]), "r"(a[1]), "r"(a[2]), "r"(a[3]), "r"(b0), "r"(b1));
}

// ---------------- scoped atomics (lstm barrier) ---------------------------------
__device__ __forceinline__ unsigned atom_add_acqrel(unsigned* p, unsigned v) {
    unsigned old;
    asm volatile("atom.acq_rel.gpu.global.add.u32 %0, [%1], %2;"
                 : "=r"(old) : "l"(p), "r"(v) : "memory");
    return old;
}
__device__ __forceinline__ unsigned ld_acquire(unsigned* p) {
    unsigned v;
    asm volatile("ld.acquire.gpu.global.u32 %0, [%1];" : "=r"(v) : "l"(p) : "memory");
    return v;
}
__device__ __forceinline__ void st_release_u32(unsigned* p, unsigned v) {
    asm volatile("st.release.gpu.global.u32 [%0], %1;" :: "l"(p), "r"(v) : "memory");
}

// ---------------- index helpers -------------------------------------------------
__device__ __forceinline__ long long ld_idx(const void* p, int i, bool is64) {
    return is64 ? ((const long long*)p)[i] : (long long)((const int*)p)[i];
}
__device__ __forceinline__ bool detect_is64(const void* start_ids) {
    return ((const int*)start_ids)[1] == 0;
}

// ---------------- K0: per-batch metadata ----------------------------------------
__global__ void meta_kernel(const void* start_ids, const void* masks) {
    int b = blockIdx.x;
    int tid = threadIdx.x;
    bool is64 = detect_is64(start_ids);
    __shared__ int red[256];
    int cnt = 0, sm = 0;
    for (int t = tid; t < SN; t += 256) {
        long long sv = ld_idx(start_ids, b * SN + t, is64);
        long long mv = ld_idx(masks, b * SN + t, is64);
        cnt += (sv >= 0);
        sm += (int)mv;
    }
    red[tid] = cnt; __syncthreads();
    for (int o = 128; o > 0; o >>= 1) { if (tid < o) red[tid] += red[tid + o]; __syncthreads(); }
    int ntot = red[0]; __syncthreads();
    red[tid] = sm; __syncthreads();
    for (int o = 128; o > 0; o >>= 1) { if (tid < o) red[tid] += red[tid + o]; __syncthreads(); }
    int stot = red[0];
    if (tid == 0) {
        g_n[b] = ntot;
        g_sent[b] = stot;
        long long last = 0;
        if (ntot > 0) last = ld_idx(start_ids, b * SN + ntot - 1, is64);
        g_last[b] = (int)last;
    }
}

// ---------------- K1: align gather + bf16 hi/lo split ----------------------------
__global__ void gather_kernel(const float* __restrict__ hs, const void* __restrict__ start_ids) {
    int t = blockIdx.x, b = blockIdx.y;
    int sent = g_sent[b];
    if (t >= sent) return;   // rows t >= sent stay zero in g_eh/g_el (static zero init)
    bool is64 = detect_is64(start_ids);
    int n = g_n[b];
    long long idx;
    if (t == 0)      idx = 0;
    else if (t < n)  idx = ld_idx(start_ids, b * SN + t, is64) - 1;
    else if (t == n) idx = g_last[b];
    else             idx = 0;
    if (idx < 0) idx = 0;
    if (idx > SN - 1) idx = SN - 1;
    const float4* src = (const float4*)(hs + ((size_t)b * SN + (size_t)idx) * DN);
    float4 v = src[threadIdx.x];
    size_t base = ((size_t)b * SN + t) * DN + threadIdx.x * 4;
    float e[4] = {v.x, v.y, v.z, v.w};
    __nv_bfloat16 h4[4], l4[4];
    #pragma unroll
    for (int i = 0; i < 4; i++) {
        h4[i] = __float2bfloat16(e[i]);
        l4[i] = __float2bfloat16(e[i] - __bfloat162float(h4[i]));
    }
    *(__nv_bfloat162*)&g_eh[base]     = __nv_bfloat162(h4[0], h4[1]);
    *(__nv_bfloat162*)&g_eh[base + 2] = __nv_bfloat162(h4[2], h4[3]);
    *(__nv_bfloat162*)&g_el[base]     = __nv_bfloat162(l4[0], l4[1]);
    *(__nv_bfloat162*)&g_el[base + 2] = __nv_bfloat162(l4[2], l4[3]);
}

// ---------------- K1b: Wih hi/lo split -------------------------------------------
__global__ void wconv_kernel(const float* __restrict__ Wf, const float* __restrict__ Wb) {
    int idx = (blockIdx.x * 256 + threadIdx.x) * 4;
    const int half = GN * DN;
    const float* src = (idx < half) ? (Wf + idx) : (Wb + (idx - half));
    float4 v = *(const float4*)src;
    float e[4] = {v.x, v.y, v.z, v.w};
    #pragma unroll
    for (int i = 0; i < 4; i++) {
        __nv_bfloat16 h = __float2bfloat16(e[i]);
        g_Wh[idx + i] = h;
        g_Wl[idx + i] = __float2bfloat16(e[i] - __bfloat162float(h));
    }
}

// ---------------- K2: input projection via bf16 split-3 tensor-core GEMM ---------
// Block tile 64(t) x 128(n), 8 warps (2m x 4n), warp tile 32x32 as m16n8k16 frags.
// D = Ah*Bh + Ah*Bl + Al*Bh (fp32 accum) == fp32 GEMM to ~2^-18 relative.
__global__ void __launch_bounds__(256, 2) projmma_kernel(
    const float* __restrict__ bihf, const float* __restrict__ bhhf,
    const float* __restrict__ bihb, const float* __restrict__ bhhb)
{
    int b = blockIdx.z & 63;
    int dir = blockIdx.z >> 6;
    int sent = g_sent[b];
    int t0 = blockIdx.y * 64;
    if (t0 >= sent) return;
    int n0 = blockIdx.x * 128;

    const float* bih = dir ? bihb : bihf;
    const float* bhh = dir ? bhhb : bhhf;

    extern __shared__ __nv_bfloat16 smb[];
    // per stage (15360 bf16): Ash[64][40] @0, Asl @2560, Bsh[128][40] @5120, Bsl @10240

    int tid = threadIdx.x;
    int warp = tid >> 5, lane = tid & 31;
    int wm = warp >> 2, wn = warp & 3;
    int g = lane >> 2, tig = lane & 3;

    float d[2][4][4];
    #pragma unroll
    for (int mt = 0; mt < 2; mt++)
        #pragma unroll
        for (int f = 0; f < 4; f++)
            #pragma unroll
            for (int c = 0; c < 4; c++) d[mt][f][c] = 0.f;

    const __nv_bfloat16* Eh = g_eh + ((size_t)b * SN + t0) * DN;
    const __nv_bfloat16* El = g_el + ((size_t)b * SN + t0) * DN;
    const __nv_bfloat16* Wh = g_Wh + ((size_t)dir * GN + n0) * DN;
    const __nv_bfloat16* Wl = g_Wl + ((size_t)dir * GN + n0) * DN;

    #define PJ_FILL(stg, k0)                                                              \
        do {                                                                              \
            __nv_bfloat16* S = smb + (stg) * 15360;                                       \
            {                                                                             \
                int row = tid >> 2, seg = tid & 3;                                        \
                unsigned da = (unsigned)__cvta_generic_to_shared(S + row * 40 + seg * 8); \
                asm volatile("cp.async.ca.shared.global [%0], [%1], 16;"                  \
                             :: "r"(da), "l"(Eh + (size_t)row * DN + (k0) + seg * 8));    \
                unsigned db = (unsigned)__cvta_generic_to_shared(S + 2560 + row * 40 + seg * 8); \
                asm volatile("cp.async.ca.shared.global [%0], [%1], 16;"                  \
                             :: "r"(db), "l"(El + (size_t)row * DN + (k0) + seg * 8));    \
            }                                                                             \
            _Pragma("unroll")                                                             \
            for (int jj = 0; jj < 2; jj++) {                                              \
                int i2 = tid + jj * 256;                                                  \
                int row = i2 >> 2, seg = i2 & 3;                                          \
                unsigned dc = (unsigned)__cvta_generic_to_shared(S + 5120 + row * 40 + seg * 8); \
                asm volatile("cp.async.ca.shared.global [%0], [%1], 16;"                  \
                             :: "r"(dc), "l"(Wh + (size_t)row * DN + (k0) + seg * 8));    \
                unsigned dd = (unsigned)__cvta_generic_to_shared(S + 10240 + row * 40 + seg * 8); \
                asm volatile("cp.async.ca.shared.global [%0], [%1], 16;"                  \
                             :: "r"(dd), "l"(Wl + (size_t)row * DN + (k0) + seg * 8));    \
            }                                                                             \
            asm volatile("cp.async.commit_group;");                                       \
        } while (0)

    PJ_FILL(0, 0);
    int st = 0;
    for (int k0 = 0; k0 < DN; k0 += 32) {
        if (k0 + 32 < DN) {
            PJ_FILL(st ^ 1, k0 + 32);
            asm volatile("cp.async.wait_group 1;");
        } else {
            asm volatile("cp.async.wait_group 0;");
        }
        __syncthreads();

        const __nv_bfloat16* S = smb + st * 15360;
        const unsigned* Ah = (const unsigned*)(S);
        const unsigned* Al = (const unsigned*)(S + 2560);
        const unsigned* Bh = (const unsigned*)(S + 5120);
        const unsigned* Bl = (const unsigned*)(S + 10240);
        // u32 row stride = 20 (40 bf16)

        #pragma unroll
        for (int s16 = 0; s16 < 2; s16++) {
            int kk = s16 * 8 + tig;          // u32 index of k-pair
            unsigned ah[2][4], al[2][4];
            #pragma unroll
            for (int mt = 0; mt < 2; mt++) {
                int r = wm * 32 + mt * 16 + g;
                ah[mt][0] = Ah[r * 20 + kk];       ah[mt][1] = Ah[(r + 8) * 20 + kk];
                ah[mt][2] = Ah[r * 20 + kk + 4];   ah[mt][3] = Ah[(r + 8) * 20 + kk + 4];
                al[mt][0] = Al[r * 20 + kk];       al[mt][1] = Al[(r + 8) * 20 + kk];
                al[mt][2] = Al[r * 20 + kk + 4];   al[mt][3] = Al[(r + 8) * 20 + kk + 4];
            }
            #pragma unroll
            for (int f = 0; f < 4; f++) {
                int c = wn * 32 + f * 8 + g;
                unsigned bh0 = Bh[c * 20 + kk], bh1 = Bh[c * 20 + kk + 4];
                unsigned bl0 = Bl[c * 20 + kk], bl1 = Bl[c * 20 + kk + 4];
                #pragma unroll
                for (int mt = 0; mt < 2; mt++) {
                    mma_bf16(d[mt][f], ah[mt], bh0, bh1);
                    mma_bf16(d[mt][f], ah[mt], bl0, bl1);
                    mma_bf16(d[mt][f], al[mt], bh0, bh1);
                }
            }
        }
        __syncthreads();
        st ^= 1;
    }
    #undef PJ_FILL

    // epilogue: bias + store valid rows
    #pragma unroll
    for (int f = 0; f < 4; f++) {
        int n = n0 + wn * 32 + f * 8 + 2 * tig;
        float bs0 = bih[n] + bhh[n];
        float bs1 = bih[n + 1] + bhh[n + 1];
        #pragma unroll
        for (int mt = 0; mt < 2; mt++) {
            int r0 = t0 + wm * 32 + mt * 16 + g;
            if (r0 < sent) {
                float2 v = make_float2(d[mt][f][0] + bs0, d[mt][f][1] + bs1);
                *(float2*)&g_xg[((size_t)(dir * SN + r0) * BN + b) * GN + n] = v;
            }
            int r1 = r0 + 8;
            if (r1 < sent) {
                float2 v = make_float2(d[mt][f][2] + bs0, d[mt][f][3] + bs1);
                *(float2*)&g_xg[((size_t)(dir * SN + r1) * BN + b) * GN + n] = v;
            }
        }
    }
}

// ---------------- K3: persistent LSTM — EXACT proven R7 flat kernel ---------------
__global__ void __launch_bounds__(256, 2) lstm_kernel(
    const float* __restrict__ Whhf, const float* __restrict__ Whhb,
    const float* __restrict__ bihf, const float* __restrict__ bhhf,
    const float* __restrict__ bihb, const float* __restrict__ bhhb,
    const float* __restrict__ h0, const float* __restrict__ c0)
{
    extern __shared__ float sm_[];
    float* ws     = sm_;                          // 48*388 = 18624
    float* hsm    = sm_ + 18624;                  // 16*388 = 6208
    float* P      = sm_ + 18624 + 6208;           // 4*48*17 = 3264
    float* bias_s = P + 3264;                     // 48
    int*   sent_s = (int*)(bias_s + 48);          // 16

    int tid = threadIdx.x;
    int blk = blockIdx.x;
    int dir = blk >> 7;
    int r7  = blk & 127;
    int bg  = r7 >> 5;
    int u0  = (r7 & 31) * 12;

    const float* Whh = dir ? Whhb : Whhf;
    const float* bih = dir ? bihb : bihf;
    const float* bhh = dir ? bhhb : bhhf;

    for (int idx = tid; idx < 48 * HN; idx += 256) {
        int r = idx / HN, k = idx % HN;
        int grow = (r / 12) * HN + u0 + (r % 12);
        ws[r * 388 + k] = Whh[(size_t)grow * HN + k];
    }
    if (tid < 48) {
        int grow = (tid / 12) * HN + u0 + (tid % 12);
        bias_s[tid] = bih[grow] + bhh[grow];
    }
    if (tid < 16) sent_s[tid] = g_sent[bg * 16 + tid];

    bool cellv = (tid < 192);
    int lb = tid / 12, u = tid % 12;
    int gb = bg * 16 + lb;
    int gj = u0 + u;
    float creg = 0.f;
    if (cellv) {
        g_h[((dir * 2 + 0) * BN + gb) * HN + gj] = h0[((size_t)dir * BN + gb) * HN + gj];
        creg = c0[((size_t)dir * BN + gb) * HN + gj];
    }

    int w    = tid >> 5;
    int ks   = w >> 1;
    int rg   = w & 1;
    int lane = tid & 31;
    int bq   = lane >> 3;
    int rs   = lane & 7;
    int kbase = ks * 96;
    int r0 = rg * 24 + rs * 3;
    const float* wr0 = &ws[(r0 + 0) * 388 + kbase];
    const float* wr1 = &ws[(r0 + 1) * 388 + kbase];
    const float* wr2 = &ws[(r0 + 2) * 388 + kbase];

    int gid = dir * 4 + bg;
    unsigned my_gen = 0;
    if (tid == 0) my_gen = ld_acquire(&g_bgen[gid]);
    __syncthreads();
    if (tid == 0) {
        __threadfence();
        unsigned old = atom_add_acqrel(&g_bcnt[gid], 1u);
        if (((old + 1) & 31u) == 0u) st_release_u32(&g_bgen[gid], my_gen + 1);
        else while (ld_acquire(&g_bgen[gid]) == my_gen) { }
        my_gen++;
    }
    __syncthreads();

    for (int s = 0; s < SN; s++) {
        int p = s & 1;
        int t = dir ? (SN - 1 - s) : s;

        float xp[4];
        if (cellv) {
            const float* xb = &g_xg[((size_t)(dir * SN + t) * BN + gb) * GN + gj];
            #pragma unroll
            for (int g2 = 0; g2 < 4; g2++) xp[g2] = xb[g2 * HN];
        }
        {
            const float* hsrc = g_h + (size_t)((dir * 2 + p) * BN + bg * 16) * HN;
            #pragma unroll
            for (int c = 0; c < 6; c++) {
                int idx = lane + c * 32;
                int sb = rg * 8 + idx / 24;
                int kk = (idx % 24) * 4;
                unsigned sd = (unsigned)__cvta_generic_to_shared(&hsm[sb * 388 + kbase + kk]);
                const float* gsrc = hsrc + (size_t)sb * HN + kbase + kk;
                asm volatile("cp.async.cg.shared.global [%0], [%1], 16;" :: "r"(sd), "l"(gsrc));
            }
            asm volatile("cp.async.commit_group;");
            asm volatile("cp.async.wait_group 0;");
        }
        asm volatile("bar.sync %0, 64;" :: "r"(1 + ks) : "memory");
        {
            unsigned long long acc[3][4];
            #pragma unroll
            for (int i = 0; i < 3; i++) { acc[i][0]=0ull; acc[i][1]=0ull; acc[i][2]=0ull; acc[i][3]=0ull; }
            #pragma unroll 4
            for (int kk = 0; kk < 96; kk += 4) {
                ulonglong2 hv0 = *(const ulonglong2*)&hsm[(0 * 4 + bq) * 388 + kbase + kk];
                ulonglong2 hv1 = *(const ulonglong2*)&hsm[(1 * 4 + bq) * 388 + kbase + kk];
                ulonglong2 hv2 = *(const ulonglong2*)&hsm[(2 * 4 + bq) * 388 + kbase + kk];
                ulonglong2 hv3 = *(const ulonglong2*)&hsm[(3 * 4 + bq) * 388 + kbase + kk];
                ulonglong2 w0 = *(const ulonglong2*)(wr0 + kk);
                ulonglong2 w1 = *(const ulonglong2*)(wr1 + kk);
                ulonglong2 w2 = *(const ulonglong2*)(wr2 + kk);
                acc[0][0]=fma2(hv0.x,w0.x,acc[0][0]); acc[0][0]=fma2(hv0.y,w0.y,acc[0][0]);
                acc[0][1]=fma2(hv1.x,w0.x,acc[0][1]); acc[0][1]=fma2(hv1.y,w0.y,acc[0][1]);
                acc[0][2]=fma2(hv2.x,w0.x,acc[0][2]); acc[0][2]=fma2(hv2.y,w0.y,acc[0][2]);
                acc[0][3]=fma2(hv3.x,w0.x,acc[0][3]); acc[0][3]=fma2(hv3.y,w0.y,acc[0][3]);
                acc[1][0]=fma2(hv0.x,w1.x,acc[1][0]); acc[1][0]=fma2(hv0.y,w1.y,acc[1][0]);
                acc[1][1]=fma2(hv1.x,w1.x,acc[1][1]); acc[1][1]=fma2(hv1.y,w1.y,acc[1][1]);
                acc[1][2]=fma2(hv2.x,w1.x,acc[1][2]); acc[1][2]=fma2(hv2.y,w1.y,acc[1][2]);
                acc[1][3]=fma2(hv3.x,w1.x,acc[1][3]); acc[1][3]=fma2(hv3.y,w1.y,acc[1][3]);
                acc[2][0]=fma2(hv0.x,w2.x,acc[2][0]); acc[2][0]=fma2(hv0.y,w2.y,acc[2][0]);
                acc[2][1]=fma2(hv1.x,w2.x,acc[2][1]); acc[2][1]=fma2(hv1.y,w2.y,acc[2][1]);
                acc[2][2]=fma2(hv2.x,w2.x,acc[2][2]); acc[2][2]=fma2(hv2.y,w2.y,acc[2][2]);
                acc[2][3]=fma2(hv3.x,w2.x,acc[2][3]); acc[2][3]=fma2(hv3.y,w2.y,acc[2][3]);
            }
            #pragma unroll
            for (int i = 0; i < 3; i++)
                #pragma unroll
                for (int j = 0; j < 4; j++)
                    P[(ks * 48 + r0 + i) * 17 + j * 4 + bq] = unpack_sum(acc[i][j]);
        }
        __syncthreads();

        float hv = 0.f;
        if (cellv) {
            bool valid = (t < sent_s[lb]);
            float g4[4];
            #pragma unroll
            for (int g2 = 0; g2 < 4; g2++) {
                int r = g2 * 12 + u;
                float sum = P[(0 * 48 + r) * 17 + lb] + P[(1 * 48 + r) * 17 + lb]
                          + P[(2 * 48 + r) * 17 + lb] + P[(3 * 48 + r) * 17 + lb];
                g4[g2] = sum + (valid ? xp[g2] : bias_s[r]);
            }
            float ig = sig_fast(g4[0]), fg = sig_fast(g4[1]);
            float cg = tanh_fast(g4[2]), og = sig_fast(g4[3]);
            creg = fg * creg + ig * cg;
            hv = og * tanh_fast(creg);
            g_h[((dir * 2 + (p ^ 1)) * BN + gb) * HN + gj] = hv;
        }
        __syncthreads();

        if (tid == 0) {
            __threadfence();
            unsigned old = atom_add_acqrel(&g_bcnt[gid], 1u);
            if (((old + 1) & 31u) == 0u) st_release_u32(&g_bgen[gid], my_gen + 1);
        }
        if (cellv)
            g_lstm[((size_t)gb * SN + t) * (2 * HN) + dir * HN + gj] = hv;
        if (tid == 0) {
            while (ld_acquire(&g_bgen[gid]) == my_gen) { }
            my_gen++;
        }
        __syncthreads();
    }
}

// ---------------- K4: output linear (Wlin cached in smem, 16 rows/block) ----------
__global__ void __launch_bounds__(256) out_kernel(
    const float* __restrict__ Wlin, const float* __restrict__ blin,
    float* __restrict__ out)
{
    extern __shared__ float Wl[];
    int tid = threadIdx.x;
    int lane = tid & 31, w = tid >> 5;
    for (int idx = tid; idx < TN * 768; idx += 256) Wl[idx] = Wlin[idx];
    __syncthreads();

    int base = blockIdx.x * 16;
    #pragma unroll
    for (int rr = 0; rr < 2; rr++) {
        int row = base + w * 2 + rr;
        const float* src = g_lstm + (size_t)row * 768;
        float rs[24];
        #pragma unroll
        for (int i = 0; i < 24; i++) rs[i] = src[lane + 32 * i];
        for (int o = 0; o < TN; o++) {
            const float* wr = &Wl[o * 768];
            float s = 0.f;
            #pragma unroll
            for (int i = 0; i < 24; i++) s += rs[i] * wr[lane + 32 * i];
            #pragma unroll
            for (int off = 16; off; off >>= 1) s += __shfl_down_sync(0xffffffffu, s, off);
            if (lane == 0) out[(size_t)row * TN + o] = s + blin[o];
        }
    }
}

// ---------------- launch -----------------------------------------------------------
extern "C" void kernel_launch(void* const* d_in, const int* in_sizes, int n_in,
                              void* d_out, int out_size) {
    const float* hs   = (const float*)d_in[0];
    const float* h0   = (const float*)d_in[1];
    const float* c0   = (const float*)d_in[2];
    const float* Wihf = (const float*)d_in[3];
    const float* Whhf = (const float*)d_in[4];
    const float* bihf = (const float*)d_in[5];
    const float* bhhf = (const float*)d_in[6];
    const float* Wihb = (const float*)d_in[7];
    const float* Whhb = (const float*)d_in[8];
    const float* bihb = (const float*)d_in[9];
    const float* bhhb = (const float*)d_in[10];
    const float* Wlin = (const float*)d_in[11];
    const float* blin = (const float*)d_in[12];
    const void*  sid  = d_in[13];
    const void*  msk  = d_in[14];

    meta_kernel<<<BN, 256>>>(sid, msk);
    gather_kernel<<<dim3(SN, BN), 192>>>(hs, sid);
    wconv_kernel<<<(2 * GN * DN) / (256 * 4), 256>>>(Wihf, Wihb);

    const int pj_smem = 2 * 15360 * 2;   // 61,440 B
    cudaFuncSetAttribute(projmma_kernel, cudaFuncAttributeMaxDynamicSharedMemorySize, pj_smem);
    projmma_kernel<<<dim3(GN / 128, SN / 64, 2 * BN), 256, pj_smem>>>(bihf, bhhf, bihb, bhhb);

    const int rec_smem = (48 * 388 + 16 * 388 + 4 * 48 * 17 + 48 + 16) * 4;  // 112,640 B
    cudaFuncSetAttribute(lstm_kernel, cudaFuncAttributeMaxDynamicSharedMemorySize, rec_smem);
    lstm_kernel<<<256, 256, rec_smem>>>(Whhf, Whhb, bihf, bhhf, bihb, bhhb, h0, c0);

    const int out_smem = TN * 768 * 4;
    cudaFuncSetAttribute(out_kernel, cudaFuncAttributeMaxDynamicSharedMemorySize, out_smem);
    out_kernel<<<(BN * SN) / 16, 256, out_smem>>>(Wlin, blin, (float*)d_out);
}

// round 13
// speedup vs baseline: 2.1898x; 1.2871x over previous
#include <cuda_runtime.h>
#include <cuda_bf16.h>
#include <math.h>

#define BN 64
#define SN 512
#define DN 768
#define HN 384
#define GN 1536
#define TN 22

// ---------------- scratch (static device globals; zero-initialized) ---------
__device__ __align__(256) __nv_bfloat16 g_eh[BN * SN * DN];   // embeds hi (bf16)
__device__ __align__(256) __nv_bfloat16 g_el[BN * SN * DN];   // embeds lo
__device__ __align__(256) __nv_bfloat16 g_Wh[2 * GN * DN];    // Wih hi, both dirs
__device__ __align__(256) __nv_bfloat16 g_Wl[2 * GN * DN];    // Wih lo
__device__ __align__(256) __nv_bfloat16 g_WhhH[2 * GN * HN];  // Whh hi, both dirs
__device__ __align__(256) __nv_bfloat16 g_WhhL[2 * GN * HN];  // Whh lo
__device__ __align__(256) __nv_bfloat16 g_hbH[2 * 2 * BN * HN]; // h hi [dir][par][b][k]
__device__ __align__(256) __nv_bfloat16 g_hbL[2 * 2 * BN * HN]; // h lo
__device__ float g_xg[2 * SN * BN * GN];                      // [dir][t][b][4H]
__device__ float g_lstm[BN * SN * 2 * HN];                    // [b][t][2H]
__device__ int   g_n[BN];
__device__ int   g_sent[BN];
__device__ int   g_last[BN];
__device__ unsigned g_bcnt[8];                                // monotonic, per (dir,bg)
__device__ unsigned g_bgen[8];

// ---------------- fast math helpers ---------------------------------------------
__device__ __forceinline__ unsigned long long fma2(unsigned long long a,
                                                   unsigned long long b,
                                                   unsigned long long c) {
    unsigned long long d;
    asm("fma.rn.f32x2 %0, %1, %2, %3;" : "=l"(d) : "l"(a), "l"(b), "l"(c));
    return d;
}
__device__ __forceinline__ float unpack_sum(unsigned long long v) {
    float lo, hi;
    asm("mov.b64 {%0, %1}, %2;" : "=f"(lo), "=f"(hi) : "l"(v));
    return lo + hi;
}
__device__ __forceinline__ float tanh_fast(float x) {
    float y;
    asm("tanh.approx.f32 %0, %1;" : "=f"(y) : "f"(x));
    return y;
}
__device__ __forceinline__ float sig_fast(float x) {
    return 0.5f * tanh_fast(0.5f * x) + 0.5f;
}

// bf16 mma: D += A(16x16,row) * B(16x8,col), fp32 accum
__device__ __forceinline__ void mma_bf16(float (&d)[4], const unsigned (&a)[4],
                                         unsigned b0, unsigned b1) {
    asm volatile(
        "mma.sync.aligned.m16n8k16.row.col.f32.bf16.bf16.f32 "
        "{%0,%1,%2,%3},{%4,%5,%6,%7},{%8,%9},{%0,%1,%2,%3};"
        : "+f"(d[0]), "+f"(d[1]), "+f"(d[2]), "+f"(d[3])
        : "r"(a[0]), "r"(a[1]), "r"(a[2]), "r"(a[3]), "r"(b0), "r"(b1));
}

// ---------------- scoped atomics (lstm barrier) ---------------------------------
__device__ __forceinline__ unsigned atom_add_acqrel(unsigned* p, unsigned v) {
    unsigned old;
    asm volatile("atom.acq_rel.gpu.global.add.u32 %0, [%1], %2;"
                 : "=r"(old) : "l"(p), "r"(v) : "memory");
    return old;
}
__device__ __forceinline__ unsigned ld_acquire(unsigned* p) {
    unsigned v;
    asm volatile("ld.acquire.gpu.global.u32 %0, [%1];" : "=r"(v) : "l"(p) : "memory");
    return v;
}
__device__ __forceinline__ void st_release_u32(unsigned* p, unsigned v) {
    asm volatile("st.release.gpu.global.u32 [%0], %1;" :: "l"(p), "r"(v) : "memory");
}

// ---------------- index helpers -------------------------------------------------
__device__ __forceinline__ long long ld_idx(const void* p, int i, bool is64) {
    return is64 ? ((const long long*)p)[i] : (long long)((const int*)p)[i];
}
__device__ __forceinline__ bool detect_is64(const void* start_ids) {
    return ((const int*)start_ids)[1] == 0;
}

// ---------------- K0: per-batch metadata ----------------------------------------
__global__ void meta_kernel(const void* start_ids, const void* masks) {
    int b = blockIdx.x;
    int tid = threadIdx.x;
    bool is64 = detect_is64(start_ids);
    __shared__ int red[256];
    int cnt = 0, sm = 0;
    for (int t = tid; t < SN; t += 256) {
        long long sv = ld_idx(start_ids, b * SN + t, is64);
        long long mv = ld_idx(masks, b * SN + t, is64);
        cnt += (sv >= 0);
        sm += (int)mv;
    }
    red[tid] = cnt; __syncthreads();
    for (int o = 128; o > 0; o >>= 1) { if (tid < o) red[tid] += red[tid + o]; __syncthreads(); }
    int ntot = red[0]; __syncthreads();
    red[tid] = sm; __syncthreads();
    for (int o = 128; o > 0; o >>= 1) { if (tid < o) red[tid] += red[tid + o]; __syncthreads(); }
    int stot = red[0];
    if (tid == 0) {
        g_n[b] = ntot;
        g_sent[b] = stot;
        long long last = 0;
        if (ntot > 0) last = ld_idx(start_ids, b * SN + ntot - 1, is64);
        g_last[b] = (int)last;
    }
}

// ---------------- K1: align gather + bf16 hi/lo split ----------------------------
__global__ void gather_kernel(const float* __restrict__ hs, const void* __restrict__ start_ids) {
    int t = blockIdx.x, b = blockIdx.y;
    int sent = g_sent[b];
    if (t >= sent) return;   // rows t >= sent stay zero (static zero init, never written)
    bool is64 = detect_is64(start_ids);
    int n = g_n[b];
    long long idx;
    if (t == 0)      idx = 0;
    else if (t < n)  idx = ld_idx(start_ids, b * SN + t, is64) - 1;
    else if (t == n) idx = g_last[b];
    else             idx = 0;
    if (idx < 0) idx = 0;
    if (idx > SN - 1) idx = SN - 1;
    const float4* src = (const float4*)(hs + ((size_t)b * SN + (size_t)idx) * DN);
    float4 v = src[threadIdx.x];
    size_t base = ((size_t)b * SN + t) * DN + threadIdx.x * 4;
    float e[4] = {v.x, v.y, v.z, v.w};
    __nv_bfloat16 h4[4], l4[4];
    #pragma unroll
    for (int i = 0; i < 4; i++) {
        h4[i] = __float2bfloat16(e[i]);
        l4[i] = __float2bfloat16(e[i] - __bfloat162float(h4[i]));
    }
    *(__nv_bfloat162*)&g_eh[base]     = __nv_bfloat162(h4[0], h4[1]);
    *(__nv_bfloat162*)&g_eh[base + 2] = __nv_bfloat162(h4[2], h4[3]);
    *(__nv_bfloat162*)&g_el[base]     = __nv_bfloat162(l4[0], l4[1]);
    *(__nv_bfloat162*)&g_el[base + 2] = __nv_bfloat162(l4[2], l4[3]);
}

// ---------------- K1b: Wih hi/lo split -------------------------------------------
__global__ void wconv_kernel(const float* __restrict__ Wf, const float* __restrict__ Wb) {
    int idx = (blockIdx.x * 256 + threadIdx.x) * 4;
    const int half = GN * DN;
    const float* src = (idx < half) ? (Wf + idx) : (Wb + (idx - half));
    float4 v = *(const float4*)src;
    float e[4] = {v.x, v.y, v.z, v.w};
    #pragma unroll
    for (int i = 0; i < 4; i++) {
        __nv_bfloat16 h = __float2bfloat16(e[i]);
        g_Wh[idx + i] = h;
        g_Wl[idx + i] = __float2bfloat16(e[i] - __bfloat162float(h));
    }
}

// ---------------- K1c: Whh hi/lo split -------------------------------------------
__global__ void wconv_hh_kernel(const float* __restrict__ Wf, const float* __restrict__ Wb) {
    int idx = (blockIdx.x * 256 + threadIdx.x) * 4;
    const int half = GN * HN;
    const float* src = (idx < half) ? (Wf + idx) : (Wb + (idx - half));
    float4 v = *(const float4*)src;
    float e[4] = {v.x, v.y, v.z, v.w};
    #pragma unroll
    for (int i = 0; i < 4; i++) {
        __nv_bfloat16 h = __float2bfloat16(e[i]);
        g_WhhH[idx + i] = h;
        g_WhhL[idx + i] = __float2bfloat16(e[i] - __bfloat162float(h));
    }
}

// ---------------- K2: input projection via bf16 split-3 tensor-core GEMM ---------
__global__ void __launch_bounds__(256, 2) projmma_kernel(
    const float* __restrict__ bihf, const float* __restrict__ bhhf,
    const float* __restrict__ bihb, const float* __restrict__ bhhb)
{
    int b = blockIdx.z & 63;
    int dir = blockIdx.z >> 6;
    int sent = g_sent[b];
    int t0 = blockIdx.y * 64;
    if (t0 >= sent) return;
    int n0 = blockIdx.x * 128;

    const float* bih = dir ? bihb : bihf;
    const float* bhh = dir ? bhhb : bhhf;

    extern __shared__ __nv_bfloat16 smb[];

    int tid = threadIdx.x;
    int warp = tid >> 5, lane = tid & 31;
    int wm = warp >> 2, wn = warp & 3;
    int g = lane >> 2, tig = lane & 3;

    float d[2][4][4];
    #pragma unroll
    for (int mt = 0; mt < 2; mt++)
        #pragma unroll
        for (int f = 0; f < 4; f++)
            #pragma unroll
            for (int c = 0; c < 4; c++) d[mt][f][c] = 0.f;

    const __nv_bfloat16* Eh = g_eh + ((size_t)b * SN + t0) * DN;
    const __nv_bfloat16* El = g_el + ((size_t)b * SN + t0) * DN;
    const __nv_bfloat16* Wh = g_Wh + ((size_t)dir * GN + n0) * DN;
    const __nv_bfloat16* Wl = g_Wl + ((size_t)dir * GN + n0) * DN;

    #define PJ_FILL(stg, k0)                                                              \
        do {                                                                              \
            __nv_bfloat16* S = smb + (stg) * 15360;                                       \
            {                                                                             \
                int row = tid >> 2, seg = tid & 3;                                        \
                unsigned da = (unsigned)__cvta_generic_to_shared(S + row * 40 + seg * 8); \
                asm volatile("cp.async.ca.shared.global [%0], [%1], 16;"                  \
                             :: "r"(da), "l"(Eh + (size_t)row * DN + (k0) + seg * 8));    \
                unsigned db = (unsigned)__cvta_generic_to_shared(S + 2560 + row * 40 + seg * 8); \
                asm volatile("cp.async.ca.shared.global [%0], [%1], 16;"                  \
                             :: "r"(db), "l"(El + (size_t)row * DN + (k0) + seg * 8));    \
            }                                                                             \
            _Pragma("unroll")                                                             \
            for (int jj = 0; jj < 2; jj++) {                                              \
                int i2 = tid + jj * 256;                                                  \
                int row = i2 >> 2, seg = i2 & 3;                                          \
                unsigned dc = (unsigned)__cvta_generic_to_shared(S + 5120 + row * 40 + seg * 8); \
                asm volatile("cp.async.ca.shared.global [%0], [%1], 16;"                  \
                             :: "r"(dc), "l"(Wh + (size_t)row * DN + (k0) + seg * 8));    \
                unsigned dd = (unsigned)__cvta_generic_to_shared(S + 10240 + row * 40 + seg * 8); \
                asm volatile("cp.async.ca.shared.global [%0], [%1], 16;"                  \
                             :: "r"(dd), "l"(Wl + (size_t)row * DN + (k0) + seg * 8));    \
            }                                                                             \
            asm volatile("cp.async.commit_group;");                                       \
        } while (0)

    PJ_FILL(0, 0);
    int st = 0;
    for (int k0 = 0; k0 < DN; k0 += 32) {
        if (k0 + 32 < DN) {
            PJ_FILL(st ^ 1, k0 + 32);
            asm volatile("cp.async.wait_group 1;");
        } else {
            asm volatile("cp.async.wait_group 0;");
        }
        __syncthreads();

        const __nv_bfloat16* S = smb + st * 15360;
        const unsigned* Ah = (const unsigned*)(S);
        const unsigned* Al = (const unsigned*)(S + 2560);
        const unsigned* Bh = (const unsigned*)(S + 5120);
        const unsigned* Bl = (const unsigned*)(S + 10240);

        #pragma unroll
        for (int s16 = 0; s16 < 2; s16++) {
            int kk = s16 * 8 + tig;
            unsigned ah[2][4], al[2][4];
            #pragma unroll
            for (int mt = 0; mt < 2; mt++) {
                int r = wm * 32 + mt * 16 + g;
                ah[mt][0] = Ah[r * 20 + kk];       ah[mt][1] = Ah[(r + 8) * 20 + kk];
                ah[mt][2] = Ah[r * 20 + kk + 4];   ah[mt][3] = Ah[(r + 8) * 20 + kk + 4];
                al[mt][0] = Al[r * 20 + kk];       al[mt][1] = Al[(r + 8) * 20 + kk];
                al[mt][2] = Al[r * 20 + kk + 4];   al[mt][3] = Al[(r + 8) * 20 + kk + 4];
            }
            #pragma unroll
            for (int f = 0; f < 4; f++) {
                int c = wn * 32 + f * 8 + g;
                unsigned bh0 = Bh[c * 20 + kk], bh1 = Bh[c * 20 + kk + 4];
                unsigned bl0 = Bl[c * 20 + kk], bl1 = Bl[c * 20 + kk + 4];
                #pragma unroll
                for (int mt = 0; mt < 2; mt++) {
                    mma_bf16(d[mt][f], ah[mt], bh0, bh1);
                    mma_bf16(d[mt][f], ah[mt], bl0, bl1);
                    mma_bf16(d[mt][f], al[mt], bh0, bh1);
                }
            }
        }
        __syncthreads();
        st ^= 1;
    }
    #undef PJ_FILL

    #pragma unroll
    for (int f = 0; f < 4; f++) {
        int n = n0 + wn * 32 + f * 8 + 2 * tig;
        float bs0 = bih[n] + bhh[n];
        float bs1 = bih[n + 1] + bhh[n + 1];
        #pragma unroll
        for (int mt = 0; mt < 2; mt++) {
            int r0 = t0 + wm * 32 + mt * 16 + g;
            if (r0 < sent) {
                float2 v = make_float2(d[mt][f][0] + bs0, d[mt][f][1] + bs1);
                *(float2*)&g_xg[((size_t)(dir * SN + r0) * BN + b) * GN + n] = v;
            }
            int r1 = r0 + 8;
            if (r1 < sent) {
                float2 v = make_float2(d[mt][f][2] + bs0, d[mt][f][3] + bs1);
                *(float2*)&g_xg[((size_t)(dir * SN + r1) * BN + b) * GN + n] = v;
            }
        }
    }
}

// ---------------- K3: persistent LSTM with tensor-core recurrence -----------------
// 256 blocks, 2/SM. dir = blk>>7; bg = (blk&127)>>5 (16 batches); u0 = (blk&31)*12
// (12 hidden units = 48 gate rows). Per step: P[16b x 48r] = h[16x384] Whh_sl^T via
// split-3 bf16 mma (warps 0-2, n-tile 16 each, full K). Whh slice resident in smem
// (bf16 hi/lo, stride 392). h exchanged via global bf16 hi/lo arrays.
// Barrier: 32 blocks per (dir,bg), monotonic absolute-gen (replay-safe).
__global__ void __launch_bounds__(256, 2) lstm_kernel(
    const float* __restrict__ bihf, const float* __restrict__ bhhf,
    const float* __restrict__ bihb, const float* __restrict__ bhhb,
    const float* __restrict__ h0, const float* __restrict__ c0)
{
    extern __shared__ char smc[];
    __nv_bfloat16* BhS = (__nv_bfloat16*)smc;                   // 48*392 = 37632 B
    __nv_bfloat16* BlS = (__nv_bfloat16*)(smc + 37632);         // 37632 B
    __nv_bfloat16* AhS = (__nv_bfloat16*)(smc + 75264);         // 16*392*2 = 12544 B
    __nv_bfloat16* AlS = (__nv_bfloat16*)(smc + 87808);         // 12544 B
    float* P      = (float*)(smc + 100352);                     // 48*17*4 = 3264 B
    float* bias_s = (float*)(smc + 103616);                     // 48*4
    int*   sent_s = (int*)(smc + 103808);                       // 16*4  (end 103872)

    int tid = threadIdx.x;
    int blk = blockIdx.x;
    int dir = blk >> 7;
    int r7  = blk & 127;
    int bg  = r7 >> 5;
    int u0  = (r7 & 31) * 12;

    const float* bih = dir ? bihb : bihf;
    const float* bhh = dir ? bhhb : bhhf;

    // one-time: Whh slice (hi/lo) into smem, stride 392 bf16 (rows 16B-aligned)
    {
        const __nv_bfloat16* WH = g_WhhH + (size_t)dir * GN * HN;
        const __nv_bfloat16* WL = g_WhhL + (size_t)dir * GN * HN;
        for (int i = tid; i < 48 * 48; i += 256) {
            int r = i / 48, c = i % 48;
            int grow = (r / 12) * HN + u0 + (r % 12);
            unsigned dh = (unsigned)__cvta_generic_to_shared(BhS + r * 392 + c * 8);
            asm volatile("cp.async.ca.shared.global [%0], [%1], 16;"
                         :: "r"(dh), "l"(WH + (size_t)grow * HN + c * 8));
            unsigned dl = (unsigned)__cvta_generic_to_shared(BlS + r * 392 + c * 8);
            asm volatile("cp.async.ca.shared.global [%0], [%1], 16;"
                         :: "r"(dl), "l"(WL + (size_t)grow * HN + c * 8));
        }
        asm volatile("cp.async.commit_group;");
    }
    if (tid < 48) {
        int grow = (tid / 12) * HN + u0 + (tid % 12);
        bias_s[tid] = bih[grow] + bhh[grow];
    }
    if (tid < 16) sent_s[tid] = g_sent[bg * 16 + tid];

    // cell ownership: tid < 192: lb = tid/12 (batch), u = tid%12 (unit)
    bool cellv = (tid < 192);
    int lb = tid / 12, u = tid % 12;
    int gb = bg * 16 + lb;
    int gj = u0 + u;
    float creg = 0.f;
    if (cellv) {
        float h0v = h0[((size_t)dir * BN + gb) * HN + gj];
        __nv_bfloat16 hh = __float2bfloat16(h0v);
        g_hbH[((dir * 2 + 0) * BN + gb) * HN + gj] = hh;
        g_hbL[((dir * 2 + 0) * BN + gb) * HN + gj] =
            __float2bfloat16(h0v - __bfloat162float(hh));
        creg = c0[((size_t)dir * BN + gb) * HN + gj];
    }

    int warp = tid >> 5, lane = tid & 31;
    int g = lane >> 2, tig = lane & 3;

    asm volatile("cp.async.wait_group 0;");

    int gid = dir * 4 + bg;
    unsigned my_gen = 0;
    if (tid == 0) my_gen = ld_acquire(&g_bgen[gid]);
    __syncthreads();
    if (tid == 0) {
        __threadfence();
        unsigned old = atom_add_acqrel(&g_bcnt[gid], 1u);
        if (((old + 1) & 31u) == 0u) st_release_u32(&g_bgen[gid], my_gen + 1);
        else while (ld_acquire(&g_bgen[gid]) == my_gen) { }
        my_gen++;
    }
    __syncthreads();

    for (int s = 0; s < SN; s++) {
        int p = s & 1;
        int t = dir ? (SN - 1 - s) : s;

        // stage h (hi/lo) for our 16 batches: 768 chunks/array, 3 per thread
        {
            const __nv_bfloat16* hH = g_hbH + (size_t)((dir * 2 + p) * BN + bg * 16) * HN;
            const __nv_bfloat16* hL = g_hbL + (size_t)((dir * 2 + p) * BN + bg * 16) * HN;
            #pragma unroll
            for (int f = 0; f < 3; f++) {
                int i2 = tid + f * 256;
                int row = i2 / 48, c = i2 % 48;
                unsigned dh = (unsigned)__cvta_generic_to_shared(AhS + row * 392 + c * 8);
                asm volatile("cp.async.cg.shared.global [%0], [%1], 16;"
                             :: "r"(dh), "l"(hH + (size_t)row * HN + c * 8));
                unsigned dl = (unsigned)__cvta_generic_to_shared(AlS + row * 392 + c * 8);
                asm volatile("cp.async.cg.shared.global [%0], [%1], 16;"
                             :: "r"(dl), "l"(hL + (size_t)row * HN + c * 8));
            }
            asm volatile("cp.async.commit_group;");
        }

        // prefetch xg (consumed in cell)
        float xp[4];
        if (cellv) {
            const float* xb = &g_xg[((size_t)(dir * SN + t) * BN + gb) * GN + gj];
            #pragma unroll
            for (int g2 = 0; g2 < 4; g2++) xp[g2] = xb[g2 * HN];
        }

        asm volatile("cp.async.wait_group 0;");
        __syncthreads();

        // mma: warps 0-2, each 16 gate rows (2 n-tiles), full K=384 (24 k-steps)
        if (warp < 3) {
            const unsigned* Ah = (const unsigned*)AhS;
            const unsigned* Al = (const unsigned*)AlS;
            const unsigned* Bh = (const unsigned*)BhS;
            const unsigned* Bl = (const unsigned*)BlS;
            int baseA0 = g * 196, baseA1 = (g + 8) * 196;
            int baseB0 = (warp * 16 + g) * 196;
            int baseB1 = (warp * 16 + 8 + g) * 196;

            float d0[4] = {0.f, 0.f, 0.f, 0.f};
            float d1[4] = {0.f, 0.f, 0.f, 0.f};
            #pragma unroll 4
            for (int kt = 0; kt < 24; kt++) {
                int kk = kt * 8 + tig;
                unsigned ah[4] = {Ah[baseA0 + kk], Ah[baseA1 + kk],
                                  Ah[baseA0 + kk + 4], Ah[baseA1 + kk + 4]};
                unsigned al[4] = {Al[baseA0 + kk], Al[baseA1 + kk],
                                  Al[baseA0 + kk + 4], Al[baseA1 + kk + 4]};
                unsigned bh00 = Bh[baseB0 + kk], bh01 = Bh[baseB0 + kk + 4];
                unsigned bh10 = Bh[baseB1 + kk], bh11 = Bh[baseB1 + kk + 4];
                unsigned bl00 = Bl[baseB0 + kk], bl01 = Bl[baseB0 + kk + 4];
                unsigned bl10 = Bl[baseB1 + kk], bl11 = Bl[baseB1 + kk + 4];
                mma_bf16(d0, ah, bh00, bh01);
                mma_bf16(d0, ah, bl00, bl01);
                mma_bf16(d0, al, bh00, bh01);
                mma_bf16(d1, ah, bh10, bh11);
                mma_bf16(d1, ah, bl10, bl11);
                mma_bf16(d1, al, bh10, bh11);
            }
            // P[r][b]: D[batch g][gate col 2tig(+1)] per n-tile
            int rb0 = warp * 16 + 2 * tig;
            P[(rb0 + 0) * 17 + g]     = d0[0];
            P[(rb0 + 1) * 17 + g]     = d0[1];
            P[(rb0 + 0) * 17 + g + 8] = d0[2];
            P[(rb0 + 1) * 17 + g + 8] = d0[3];
            int rb1 = rb0 + 8;
            P[(rb1 + 0) * 17 + g]     = d1[0];
            P[(rb1 + 1) * 17 + g]     = d1[1];
            P[(rb1 + 0) * 17 + g + 8] = d1[2];
            P[(rb1 + 1) * 17 + g + 8] = d1[3];
        }
        __syncthreads();

        // cell update
        float hv = 0.f;
        if (cellv) {
            bool valid = (t < sent_s[lb]);
            float g4[4];
            #pragma unroll
            for (int g2 = 0; g2 < 4; g2++) {
                int r = g2 * 12 + u;
                g4[g2] = P[r * 17 + lb] + (valid ? xp[g2] : bias_s[r]);
            }
            float ig = sig_fast(g4[0]), fg = sig_fast(g4[1]);
            float cg = tanh_fast(g4[2]), og = sig_fast(g4[3]);
            creg = fg * creg + ig * cg;
            hv = og * tanh_fast(creg);
            __nv_bfloat16 hh = __float2bfloat16(hv);
            size_t ho = (size_t)((dir * 2 + (p ^ 1)) * BN + gb) * HN + gj;
            g_hbH[ho] = hh;
            g_hbL[ho] = __float2bfloat16(hv - __bfloat162float(hh));
        }
        __syncthreads();

        if (tid == 0) {
            __threadfence();
            unsigned old = atom_add_acqrel(&g_bcnt[gid], 1u);
            if (((old + 1) & 31u) == 0u) st_release_u32(&g_bgen[gid], my_gen + 1);
        }
        if (cellv)
            g_lstm[((size_t)gb * SN + t) * (2 * HN) + dir * HN + gj] = hv;
        if (tid == 0) {
            while (ld_acquire(&g_bgen[gid]) == my_gen) { }
            my_gen++;
        }
        __syncthreads();
    }
}

// ---------------- K4: output linear (Wlin cached in smem, 16 rows/block) ----------
__global__ void __launch_bounds__(256) out_kernel(
    const float* __restrict__ Wlin, const float* __restrict__ blin,
    float* __restrict__ out)
{
    extern __shared__ float Wl[];
    int tid = threadIdx.x;
    int lane = tid & 31, w = tid >> 5;
    for (int idx = tid; idx < TN * 768; idx += 256) Wl[idx] = Wlin[idx];
    __syncthreads();

    int base = blockIdx.x * 16;
    #pragma unroll
    for (int rr = 0; rr < 2; rr++) {
        int row = base + w * 2 + rr;
        const float* src = g_lstm + (size_t)row * 768;
        float rs[24];
        #pragma unroll
        for (int i = 0; i < 24; i++) rs[i] = src[lane + 32 * i];
        for (int o = 0; o < TN; o++) {
            const float* wr = &Wl[o * 768];
            float s = 0.f;
            #pragma unroll
            for (int i = 0; i < 24; i++) s += rs[i] * wr[lane + 32 * i];
            #pragma unroll
            for (int off = 16; off; off >>= 1) s += __shfl_down_sync(0xffffffffu, s, off);
            if (lane == 0) out[(size_t)row * TN + o] = s + blin[o];
        }
    }
}

// ---------------- launch -----------------------------------------------------------
extern "C" void kernel_launch(void* const* d_in, const int* in_sizes, int n_in,
                              void* d_out, int out_size) {
    const float* hs   = (const float*)d_in[0];
    const float* h0   = (const float*)d_in[1];
    const float* c0   = (const float*)d_in[2];
    const float* Wihf = (const float*)d_in[3];
    const float* Whhf = (const float*)d_in[4];
    const float* bihf = (const float*)d_in[5];
    const float* bhhf = (const float*)d_in[6];
    const float* Wihb = (const float*)d_in[7];
    const float* Whhb = (const float*)d_in[8];
    const float* bihb = (const float*)d_in[9];
    const float* bhhb = (const float*)d_in[10];
    const float* Wlin = (const float*)d_in[11];
    const float* blin = (const float*)d_in[12];
    const void*  sid  = d_in[13];
    const void*  msk  = d_in[14];

    meta_kernel<<<BN, 256>>>(sid, msk);
    gather_kernel<<<dim3(SN, BN), 192>>>(hs, sid);
    wconv_kernel<<<(2 * GN * DN) / (256 * 4), 256>>>(Wihf, Wihb);
    wconv_hh_kernel<<<(2 * GN * HN) / (256 * 4), 256>>>(Whhf, Whhb);

    const int pj_smem = 2 * 15360 * 2;   // 61,440 B
    cudaFuncSetAttribute(projmma_kernel, cudaFuncAttributeMaxDynamicSharedMemorySize, pj_smem);
    projmma_kernel<<<dim3(GN / 128, SN / 64, 2 * BN), 256, pj_smem>>>(bihf, bhhf, bihb, bhhb);

    const int rec_smem = 103872;
    cudaFuncSetAttribute(lstm_kernel, cudaFuncAttributeMaxDynamicSharedMemorySize, rec_smem);
    lstm_kernel<<<256, 256, rec_smem>>>(bihf, bhhf, bihb, bhhb, h0, c0);

    const int out_smem = TN * 768 * 4;
    cudaFuncSetAttribute(out_kernel, cudaFuncAttributeMaxDynamicSharedMemorySize, out_smem);
    out_kernel<<<(BN * SN) / 16, 256, out_smem>>>(Wlin, blin, (float*)d_out);
}